// round 6
// baseline (speedup 1.0000x reference)
#include <cuda_runtime.h>
#include <cuda_bf16.h>
#include <mma.h>

using namespace nvcuda;

#define Bb 2
#define Nn 512
#define Ff 128
#define LDA 136   /* bf16 row stride for A-side tiles (pad vs bank conflicts) */
#define SCRLD 20  /* f32 scratch row stride */

typedef unsigned int u32;
typedef unsigned long long u64;
typedef __nv_bfloat16 bf16;

// ------------------------- device scratch (no allocs) -------------------------
__device__ float g_A[Bb*Nn*Ff];      // hm @ edge_w1[0:F]
__device__ float g_Bm[Bb*Nn*Ff];     // hm @ edge_w1[F:2F] + eb1
__device__ float g_hm[Bb*Nn*Ff];     // h * mask
__device__ float g_agg[Bb*Nn*Ff];    // sum_j m
__device__ float g_trans[Bb*Nn*3];
__device__ bf16  g_w2hi[Ff*Ff];      // W2 hi, [k][f]
__device__ bf16  g_w2lo[Ff*Ff];      // W2 residual
__device__ bf16  g_c1hi[Ff*Ff];      // coord_w1, [k][f]

__device__ __forceinline__ float silu_f(float x) { return x / (1.f + __expf(-x)); }

__device__ __forceinline__ u32 pkbf(float a, float b) {
    __nv_bfloat162 t = __floats2bfloat162_rn(a, b);
    return *(u32*)&t;
}

// ------------------------- SMEM layout (bytes) -------------------------
#define SM_M1HI 0                          /* 128*136*2 = 34816 */
#define SM_M1LO (SM_M1HI + 34816)
#define SM_MBUF (SM_M1LO + 34816)
#define SM_W2HI (SM_MBUF + 34816)          /* 128*128*2 = 32768 */
#define SM_W2LO (SM_W2HI + 32768)
#define SM_C1HI (SM_W2LO + 32768)
#define SM_SCR  (SM_C1HI + 32768)          /* 8 warps * 16*SCRLD*4 = 10240 */
#define SM_AJS  (SM_SCR + 10240)           /* 16*129*4 = 8256 */
#define SM_BMS  (SM_AJS + 8256)            /* 8*129*4 = 4128 */
#define SM_W1C  (SM_BMS + 4128)
#define SM_B2S  (SM_W1C + 512)
#define SM_CB1S (SM_B2S + 512)
#define SM_CW2S (SM_CB1S + 512)
#define SM_RAD  (SM_CW2S + 512)
#define SM_M2D  (SM_RAD + 512)
#define SM_EMB  (SM_M2D + 512)
#define SM_CI   (SM_EMB + 512)
#define SM_MI   (SM_CI + 96)
#define SM_CJ   (SM_MI + 32)
#define SM_MJ   (SM_CJ + 192)
#define SM_TRS  (SM_MJ + 64)
#define SM_TOTAL (SM_TRS + 96)

// ---------------------------------------------------------------------------
// k_prep: hm = h*mask ; A = hm @ W1a ; Bm = hm @ W1b + b1
// ---------------------------------------------------------------------------
__global__ __launch_bounds__(128) void k_prep(
    const float* __restrict__ h, const float* __restrict__ mask,
    const float* __restrict__ ew1, const float* __restrict__ eb1)
{
    __shared__ float hr[Ff];
    const int r = blockIdx.x;
    const int t = threadIdx.x;
    const float mk = mask[r];
    float hv = h[r*Ff + t] * mk;
    hr[t] = hv;
    g_hm[r*Ff + t] = hv;
    __syncthreads();
    float a = 0.f;
    float bm = eb1[t];
    #pragma unroll 8
    for (int k = 0; k < Ff; k++) {
        float hk = hr[k];
        a  += hk * ew1[k*Ff + t];
        bm += hk * ew1[(Ff + k)*Ff + t];
    }
    g_A[r*Ff + t]  = a;
    g_Bm[r*Ff + t] = bm;
}

// ---------------------------------------------------------------------------
// k_wprep: hi/lo split of W2, bf16 copy of coord_w1 (plain [k][f] layout)
// ---------------------------------------------------------------------------
__global__ __launch_bounds__(256) void k_wprep(
    const float* __restrict__ ew2, const float* __restrict__ cw1)
{
    for (int idx = blockIdx.x*256 + threadIdx.x; idx < 2*Ff*Ff; idx += gridDim.x*256) {
        int mat = idx >> 14, rem = idx & 16383;
        if (mat == 0) {
            float v = ew2[rem];
            bf16 hi = __float2bfloat16_rn(v);
            g_w2hi[rem] = hi;
            g_w2lo[rem] = __float2bfloat16_rn(v - __bfloat162float(hi));
        } else {
            g_c1hi[rem] = __float2bfloat16_rn(cw1[rem]);
        }
    }
}

// ---------------------------------------------------------------------------
// k_edge: fused edge+coord models with wmma bf16 HMMA
// grid = B*(N/8) = 128 blocks, 256 threads (8 warps; warp w owns node i0+w)
// ---------------------------------------------------------------------------
__global__ __launch_bounds__(256, 1) void k_edge(
    const float* __restrict__ coord, const float* __restrict__ mask,
    const float* __restrict__ ew1,   const float* __restrict__ eb2,
    const float* __restrict__ cb1,   const float* __restrict__ cw2)
{
    extern __shared__ char smc[];
    bf16*  m1hi = (bf16*)(smc + SM_M1HI);
    bf16*  m1lo = (bf16*)(smc + SM_M1LO);
    bf16*  mbuf = (bf16*)(smc + SM_MBUF);
    bf16*  W2hi = (bf16*)(smc + SM_W2HI);
    bf16*  W2lo = (bf16*)(smc + SM_W2LO);
    bf16*  C1hi = (bf16*)(smc + SM_C1HI);
    float* Ajs  = (float*)(smc + SM_AJS);
    float* Bms  = (float*)(smc + SM_BMS);
    float* w1c  = (float*)(smc + SM_W1C);
    float* b2s  = (float*)(smc + SM_B2S);
    float* cb1s = (float*)(smc + SM_CB1S);
    float* cw2s = (float*)(smc + SM_CW2S);
    float* rad  = (float*)(smc + SM_RAD);
    float* m2d  = (float*)(smc + SM_M2D);
    float* emb  = (float*)(smc + SM_EMB);
    float* ci   = (float*)(smc + SM_CI);
    float* mi   = (float*)(smc + SM_MI);
    float* cj   = (float*)(smc + SM_CJ);
    float* mj   = (float*)(smc + SM_MJ);
    float* trs  = (float*)(smc + SM_TRS);

    const int tid = threadIdx.x;
    const int w   = tid >> 5, l = tid & 31;
    const int jj  = l >> 1;              // row within warp tile (j index)
    const int c0  = (l & 1) * 8;         // column sub-offset within 16-col tile
    const int b   = blockIdx.x >> 6;
    const int i0  = (blockIdx.x & 63) * 8;
    float* scr = (float*)(smc + SM_SCR) + w * 16 * SCRLD;

    // --- stage weights into SMEM ---
    {
        uint4* s1 = (uint4*)W2hi; uint4* s2 = (uint4*)W2lo; uint4* s3 = (uint4*)C1hi;
        const uint4* d1 = (const uint4*)g_w2hi;
        const uint4* d2 = (const uint4*)g_w2lo;
        const uint4* d3 = (const uint4*)g_c1hi;
        for (int i = tid; i < 2048; i += 256) { s1[i] = d1[i]; s2[i] = d2[i]; s3[i] = d3[i]; }
    }
    if (tid < Ff) {
        w1c[tid]  = ew1[2*Ff*Ff + tid];
        b2s[tid]  = eb2[tid];
        cb1s[tid] = cb1[tid];
        cw2s[tid] = cw2[tid];
    }
    if (tid < 8) {
        float mk = mask[b*Nn + i0 + tid];
        mi[tid] = mk;
        ci[tid*3+0] = coord[(b*Nn+i0+tid)*3+0]*mk;
        ci[tid*3+1] = coord[(b*Nn+i0+tid)*3+1]*mk;
        ci[tid*3+2] = coord[(b*Nn+i0+tid)*3+2]*mk;
    }
    if (tid < 24) trs[tid] = 0.f;
    for (int idx = tid; idx < 8*Ff; idx += 256) {
        int ii = idx >> 7, f = idx & 127;
        Bms[ii*129 + f] = g_Bm[(b*Nn + i0 + ii)*Ff + f];
    }

    float agg[64];
    #pragma unroll
    for (int q = 0; q < 64; q++) agg[q] = 0.f;

    for (int jt = 0; jt < Nn/16; jt++) {
        const int j0 = jt*16;
        __syncthreads();   // protects Ajs/cj/mj vs previous-iteration readers
        for (int idx = tid; idx < 16*Ff; idx += 256) {
            int j = idx >> 7, f = idx & 127;
            Ajs[j*129 + f] = g_A[(b*Nn + j0 + j)*Ff + f];
        }
        if (tid < 16) {
            float mk = mask[b*Nn + j0 + tid];
            mj[tid] = mk;
            cj[tid*3+0] = coord[(b*Nn+j0+tid)*3+0]*mk;
            cj[tid*3+1] = coord[(b*Nn+j0+tid)*3+1]*mk;
            cj[tid*3+2] = coord[(b*Nn+j0+tid)*3+2]*mk;
        }
        __syncthreads();

        // ---- per-warp: radial + mask2d for this warp's 16 edges ----
        if (l < 16) {
            float m2 = mi[w]*mj[l];
            float dx = ci[w*3+0]-cj[l*3+0];
            float dy = ci[w*3+1]-cj[l*3+1];
            float dz = ci[w*3+2]-cj[l*3+2];
            rad[w*16+l] = (dx*dx + dy*dy + dz*dz)*m2;
            m2d[w*16+l] = m2;
        }
        __syncwarp();

        // ---- build m1 hi/lo (warp-local rows) ----
        {
            const int fh = (l & 1) * 64;
            const int row = w*16 + jj;
            const float* Aj = Ajs + jj*129 + fh;
            const float* Bm = Bms + w*129 + fh;
            const float  rv = rad[w*16 + jj];
            #pragma unroll
            for (int c = 0; c < 8; c++) {
                float x[8];
                #pragma unroll
                for (int q = 0; q < 8; q++) {
                    int k = c*8 + q;
                    x[q] = silu_f(Aj[k] + Bm[k] + rv*w1c[fh + k]);
                }
                bf16 hi[8];
                #pragma unroll
                for (int q = 0; q < 8; q++) hi[q] = __float2bfloat16_rn(x[q]);
                uint4 vh, vl;
                vh.x = (*(unsigned short*)&hi[0]) | ((u32)(*(unsigned short*)&hi[1]) << 16);
                vh.y = (*(unsigned short*)&hi[2]) | ((u32)(*(unsigned short*)&hi[3]) << 16);
                vh.z = (*(unsigned short*)&hi[4]) | ((u32)(*(unsigned short*)&hi[5]) << 16);
                vh.w = (*(unsigned short*)&hi[6]) | ((u32)(*(unsigned short*)&hi[7]) << 16);
                vl.x = pkbf(x[0]-__bfloat162float(hi[0]), x[1]-__bfloat162float(hi[1]));
                vl.y = pkbf(x[2]-__bfloat162float(hi[2]), x[3]-__bfloat162float(hi[3]));
                vl.z = pkbf(x[4]-__bfloat162float(hi[4]), x[5]-__bfloat162float(hi[5]));
                vl.w = pkbf(x[6]-__bfloat162float(hi[6]), x[7]-__bfloat162float(hi[7]));
                int eoff = row*LDA + fh + c*8;
                *(uint4*)(m1hi + eoff) = vh;
                *(uint4*)(m1lo + eoff) = vl;
            }
        }
        __syncwarp();

        // ---- GEMM2: m = silu(m1 @ W2 + b2) * m2d  (3-term hi/lo split) ----
        {
            const bf16* Abase_hi = m1hi + (w*16)*LDA;
            const bf16* Abase_lo = m1lo + (w*16)*LDA;
            const float m2v = m2d[w*16 + jj];
            #pragma unroll
            for (int nt = 0; nt < 8; nt++) {
                wmma::fragment<wmma::accumulator, 16, 16, 16, float> acc;
                wmma::fill_fragment(acc, 0.f);
                #pragma unroll
                for (int k0 = 0; k0 < 8; k0++) {
                    wmma::fragment<wmma::matrix_a, 16, 16, 16, bf16, wmma::row_major> ah, al;
                    wmma::fragment<wmma::matrix_b, 16, 16, 16, bf16, wmma::row_major> bh, bl;
                    wmma::load_matrix_sync(ah, Abase_hi + k0*16, LDA);
                    wmma::load_matrix_sync(al, Abase_lo + k0*16, LDA);
                    wmma::load_matrix_sync(bh, W2hi + (k0*16)*Ff + nt*16, Ff);
                    wmma::load_matrix_sync(bl, W2lo + (k0*16)*Ff + nt*16, Ff);
                    wmma::mma_sync(acc, ah, bh, acc);
                    wmma::mma_sync(acc, ah, bl, acc);
                    wmma::mma_sync(acc, al, bh, acc);
                }
                wmma::store_matrix_sync(scr, acc, SCRLD, wmma::mem_row_major);
                __syncwarp();
                float mv[8];
                #pragma unroll
                for (int q = 0; q < 8; q++) {
                    int f = nt*16 + c0 + q;
                    float dv = scr[jj*SCRLD + c0 + q];
                    mv[q] = silu_f(dv + b2s[f]) * m2v;
                    agg[nt*8 + q] += mv[q];
                }
                uint4 vh;
                vh.x = pkbf(mv[0], mv[1]);
                vh.y = pkbf(mv[2], mv[3]);
                vh.z = pkbf(mv[4], mv[5]);
                vh.w = pkbf(mv[6], mv[7]);
                *(uint4*)(mbuf + (w*16 + jj)*LDA + nt*16 + c0) = vh;
                __syncwarp();
            }
        }

        // ---- GEMM3: embed = (silu(m @ coord_w1 + cb1)) @ cw2 ----
        {
            const bf16* Abase = mbuf + (w*16)*LDA;
            float pe = 0.f;
            #pragma unroll
            for (int nt = 0; nt < 8; nt++) {
                wmma::fragment<wmma::accumulator, 16, 16, 16, float> acc;
                wmma::fill_fragment(acc, 0.f);
                #pragma unroll
                for (int k0 = 0; k0 < 8; k0++) {
                    wmma::fragment<wmma::matrix_a, 16, 16, 16, bf16, wmma::row_major> af;
                    wmma::fragment<wmma::matrix_b, 16, 16, 16, bf16, wmma::row_major> bf_;
                    wmma::load_matrix_sync(af, Abase + k0*16, LDA);
                    wmma::load_matrix_sync(bf_, C1hi + (k0*16)*Ff + nt*16, Ff);
                    wmma::mma_sync(acc, af, bf_, acc);
                }
                wmma::store_matrix_sync(scr, acc, SCRLD, wmma::mem_row_major);
                __syncwarp();
                #pragma unroll
                for (int q = 0; q < 8; q++) {
                    int f = nt*16 + c0 + q;
                    float dv = scr[jj*SCRLD + c0 + q];
                    pe += silu_f(dv + cb1s[f]) * cw2s[f];
                }
                __syncwarp();
            }
            pe += __shfl_xor_sync(0xffffffffu, pe, 1);
            if ((l & 1) == 0) emb[w*16 + jj] = pe;
        }
        __syncthreads();

        // ---- trans accumulation (deterministic, 24 threads) ----
        if (tid < 24) {
            int ii = tid/3, d = tid - ii*3;
            float cid = ci[ii*3+d];
            float s = 0.f;
            #pragma unroll
            for (int j = 0; j < 16; j++) {
                int e = ii*16 + j;
                float m2 = m2d[e];
                s += (cid - cj[j*3+d])*m2*emb[e]*m2;
            }
            trs[tid] += s;
        }
    }
    __syncthreads();

    // ---- final agg reduction over the 16 rows (jj) of each warp ----
    #pragma unroll
    for (int q = 0; q < 64; q++) {
        float v = agg[q];
        v += __shfl_xor_sync(0xffffffffu, v, 2);
        v += __shfl_xor_sync(0xffffffffu, v, 4);
        v += __shfl_xor_sync(0xffffffffu, v, 8);
        v += __shfl_xor_sync(0xffffffffu, v, 16);
        if (jj == 0) {
            int nt = q >> 3, qq = q & 7;
            g_agg[(b*Nn + i0 + w)*Ff + nt*16 + c0 + qq] = v;
        }
    }
    if (tid < 24) g_trans[(b*Nn + i0 + tid/3)*3 + (tid % 3)] = trs[tid];
}

// ---------------------------------------------------------------------------
// k_node: node MLP + residual + coord finalize; writes d_out
// ---------------------------------------------------------------------------
__global__ __launch_bounds__(128) void k_node(
    const float* __restrict__ coord, const float* __restrict__ mask,
    const float* __restrict__ nw1, const float* __restrict__ nb1,
    const float* __restrict__ nw2, const float* __restrict__ nb2,
    float* __restrict__ out)
{
    __shared__ float nin[2*Ff];
    __shared__ float t1s[Ff];
    __shared__ float red[Ff];
    const int r = blockIdx.x;
    const int t = threadIdx.x;
    const int b = r >> 9;
    const float mk = mask[r];
    const float hm = g_hm[r*Ff + t];
    nin[t]      = hm * mk;
    nin[Ff + t] = g_agg[r*Ff + t] * mk;
    float s = 0.f;
    for (int q = t; q < Nn; q += 128) s += mask[b*Nn + q];
    red[t] = s;
    __syncthreads();
    for (int off = 64; off >= 1; off >>= 1) {
        if (t < off) red[t] += red[t + off];
        __syncthreads();
    }
    float acc = nb1[t];
    #pragma unroll 8
    for (int k = 0; k < 2*Ff; k++) acc += nin[k]*nw1[k*Ff + t];
    t1s[t] = silu_f(acc);
    __syncthreads();
    float acc2 = nb2[t];
    #pragma unroll 8
    for (int k = 0; k < Ff; k++) acc2 += t1s[k]*nw2[k*Ff + t];
    out[r*Ff + t] = (hm + acc2)*mk;
    if (t < 3) {
        float denom = mk*red[0] + 1e-10f;
        float cm = coord[r*3 + t]*mk;
        out[Bb*Nn*Ff + r*3 + t] = (cm + g_trans[r*3 + t]/denom)*mk;
    }
}

// ---------------------------------------------------------------------------
extern "C" void kernel_launch(void* const* d_in, const int* in_sizes, int n_in,
                              void* d_out, int out_size)
{
    const float* h     = (const float*)d_in[0];
    const float* coord = (const float*)d_in[1];
    const float* mask  = (const float*)d_in[2];
    const float* ew1   = (const float*)d_in[3];
    const float* eb1   = (const float*)d_in[4];
    const float* ew2   = (const float*)d_in[5];
    const float* eb2   = (const float*)d_in[6];
    const float* nw1   = (const float*)d_in[7];
    const float* nb1   = (const float*)d_in[8];
    const float* nw2   = (const float*)d_in[9];
    const float* nb2   = (const float*)d_in[10];
    const float* cw1   = (const float*)d_in[11];
    const float* cb1   = (const float*)d_in[12];
    const float* cw2   = (const float*)d_in[13];

    cudaFuncSetAttribute(k_edge, cudaFuncAttributeMaxDynamicSharedMemorySize, SM_TOTAL);

    k_prep<<<Bb*Nn, 128>>>(h, mask, ew1, eb1);
    k_wprep<<<32, 256>>>(ew2, cw1);
    k_edge<<<Bb*(Nn/8), 256, SM_TOTAL>>>(coord, mask, ew1, eb2, cb1, cw2);
    k_node<<<Bb*Nn, 128>>>(coord, mask, nw1, nb1, nw2, nb2, (float*)d_out);
}

// round 7
// speedup vs baseline: 2.5580x; 2.5580x over previous
#include <cuda_runtime.h>
#include <cuda_bf16.h>
#include <mma.h>

using namespace nvcuda;

#define Bb 2
#define Nn 512
#define Ff 128
#define LDA 136          /* element stride for all bf16 operand tiles (272B rows) */
#define ROWU4 17         /* uint4 per 136-elem bf16 row */
#define SCRLD 20         /* f32 scratch row stride */

typedef unsigned int u32;
typedef __nv_bfloat16 bf16;

// ------------------------- device scratch (no allocs) -------------------------
__device__ float g_A[Bb*Nn*Ff];
__device__ float g_Bm[Bb*Nn*Ff];
__device__ float g_hm[Bb*Nn*Ff];
__device__ float g_agg[Bb*Nn*Ff];
__device__ float g_trans[Bb*Nn*3];
__device__ bf16  g_w2hi[Ff*Ff];   // [k][f], packed 128 stride
__device__ bf16  g_w2lo[Ff*Ff];
__device__ bf16  g_c1hi[Ff*Ff];

__device__ __forceinline__ float silu_f(float x) { return x / (1.f + __expf(-x)); }
__device__ __forceinline__ u32 pkbf(float a, float b) {
    __nv_bfloat162 t = __floats2bfloat162_rn(a, b);
    return *(u32*)&t;
}

// ------------------------- SMEM layout (bytes) -------------------------
#define SM_M1HI 0                            /* 128*272 = 34816 */
#define SM_M1LO (SM_M1HI + 34816)            /* also reused as epilogue scratch */
#define SM_MBUF (SM_M1LO + 34816)
#define SM_W2HI (SM_MBUF + 34816)
#define SM_W2LO (SM_W2HI + 34816)
#define SM_C1HI (SM_W2LO + 34816)
#define SM_AJS  (SM_C1HI + 34816)            /* 16*129*4 = 8256 */
#define SM_BMS  (SM_AJS + 8256)              /* 8*129*4 = 4128 */
#define SM_W1C  (SM_BMS + 4128)
#define SM_B2S  (SM_W1C + 512)
#define SM_CB1S (SM_B2S + 512)
#define SM_CW2S (SM_CB1S + 512)
#define SM_M2D  (SM_CW2S + 512)
#define SM_EMBP (SM_M2D + 512)               /* 4*128*4 = 2048 */
#define SM_CI   (SM_EMBP + 2048)
#define SM_MI   (SM_CI + 96)
#define SM_CJ   (SM_MI + 32)
#define SM_MJ   (SM_CJ + 192)
#define SM_TRS  (SM_MJ + 64)
#define SM_TOTAL (SM_TRS + 96 + 16)

// ---------------------------------------------------------------------------
__global__ __launch_bounds__(128) void k_prep(
    const float* __restrict__ h, const float* __restrict__ mask,
    const float* __restrict__ ew1, const float* __restrict__ eb1)
{
    __shared__ float hr[Ff];
    const int r = blockIdx.x;
    const int t = threadIdx.x;
    const float mk = mask[r];
    float hv = h[r*Ff + t] * mk;
    hr[t] = hv;
    g_hm[r*Ff + t] = hv;
    __syncthreads();
    float a = 0.f;
    float bm = eb1[t];
    #pragma unroll 8
    for (int k = 0; k < Ff; k++) {
        float hk = hr[k];
        a  += hk * ew1[k*Ff + t];
        bm += hk * ew1[(Ff + k)*Ff + t];
    }
    g_A[r*Ff + t]  = a;
    g_Bm[r*Ff + t] = bm;
}

// ---------------------------------------------------------------------------
__global__ __launch_bounds__(256) void k_wprep(
    const float* __restrict__ ew2, const float* __restrict__ cw1)
{
    for (int idx = blockIdx.x*256 + threadIdx.x; idx < 2*Ff*Ff; idx += gridDim.x*256) {
        int mat = idx >> 14, rem = idx & 16383;
        if (mat == 0) {
            float v = ew2[rem];
            bf16 hi = __float2bfloat16_rn(v);
            g_w2hi[rem] = hi;
            g_w2lo[rem] = __float2bfloat16_rn(v - __bfloat162float(hi));
        } else {
            g_c1hi[rem] = __float2bfloat16_rn(cw1[rem]);
        }
    }
}

// ---------------------------------------------------------------------------
// k_edge: grid = 128 blocks, 512 threads (16 warps; warp grid 4x4 over 128x128)
// ---------------------------------------------------------------------------
__global__ __launch_bounds__(512, 1) void k_edge(
    const float* __restrict__ coord, const float* __restrict__ mask,
    const float* __restrict__ ew1,   const float* __restrict__ eb2,
    const float* __restrict__ cb1,   const float* __restrict__ cw2)
{
    extern __shared__ char smc[];
    bf16*  m1hi = (bf16*)(smc + SM_M1HI);
    bf16*  m1lo = (bf16*)(smc + SM_M1LO);
    bf16*  mbuf = (bf16*)(smc + SM_MBUF);
    bf16*  W2hi = (bf16*)(smc + SM_W2HI);
    bf16*  W2lo = (bf16*)(smc + SM_W2LO);
    bf16*  C1hi = (bf16*)(smc + SM_C1HI);
    float* Ajs  = (float*)(smc + SM_AJS);
    float* Bms  = (float*)(smc + SM_BMS);
    float* w1c  = (float*)(smc + SM_W1C);
    float* b2s  = (float*)(smc + SM_B2S);
    float* cb1s = (float*)(smc + SM_CB1S);
    float* cw2s = (float*)(smc + SM_CW2S);
    float* m2d  = (float*)(smc + SM_M2D);
    float* embP = (float*)(smc + SM_EMBP);
    float* ci   = (float*)(smc + SM_CI);
    float* mi   = (float*)(smc + SM_MI);
    float* cj   = (float*)(smc + SM_CJ);
    float* mj   = (float*)(smc + SM_MJ);
    float* trs  = (float*)(smc + SM_TRS);

    const int tid = threadIdx.x;
    const int w   = tid >> 5, l = tid & 31;
    const int wr  = w >> 2, wc = w & 3;
    const int r0  = wr * 32, c0 = wc * 32;
    const int b   = blockIdx.x >> 6;
    const int i0  = (blockIdx.x & 63) * 8;
    float* scr = (float*)(smc + SM_M1LO) + w * 16 * SCRLD;   // scratch in m1lo region

    // --- stage weights into SMEM, re-striding 128 -> 136 elems/row ---
    {
        uint4* s1 = (uint4*)W2hi; uint4* s2 = (uint4*)W2lo; uint4* s3 = (uint4*)C1hi;
        const uint4* d1 = (const uint4*)g_w2hi;
        const uint4* d2 = (const uint4*)g_w2lo;
        const uint4* d3 = (const uint4*)g_c1hi;
        for (int idx = tid; idx < 128*16; idx += 512) {
            int k = idx >> 4, u = idx & 15;
            s1[k*ROWU4 + u] = d1[idx];
            s2[k*ROWU4 + u] = d2[idx];
            s3[k*ROWU4 + u] = d3[idx];
        }
    }
    if (tid < Ff) {
        w1c[tid]  = ew1[2*Ff*Ff + tid];
        b2s[tid]  = eb2[tid];
        cb1s[tid] = cb1[tid];
        cw2s[tid] = cw2[tid];
    }
    if (tid < 8) {
        float mk = mask[b*Nn + i0 + tid];
        mi[tid] = mk;
        ci[tid*3+0] = coord[(b*Nn+i0+tid)*3+0]*mk;
        ci[tid*3+1] = coord[(b*Nn+i0+tid)*3+1]*mk;
        ci[tid*3+2] = coord[(b*Nn+i0+tid)*3+2]*mk;
    }
    if (tid < 24) trs[tid] = 0.f;
    for (int idx = tid; idx < 8*Ff; idx += 512) {
        int ii = idx >> 7, f = idx & 127;
        Bms[ii*129 + f] = g_Bm[(b*Nn + i0 + ii)*Ff + f];
    }

    float agg[2][2][8];
    #pragma unroll
    for (int fr = 0; fr < 2; fr++)
        #pragma unroll
        for (int fc = 0; fc < 2; fc++)
            #pragma unroll
            for (int q = 0; q < 8; q++) agg[fr][fc][q] = 0.f;

    for (int jt = 0; jt < Nn/16; jt++) {
        const int j0 = jt*16;
        __syncthreads();   // guards Ajs/cj/mj + embP vs previous iteration
        for (int idx = tid; idx < 16*Ff; idx += 512) {
            int jj = idx >> 7, f = idx & 127;
            Ajs[jj*129 + f] = g_A[(b*Nn + j0 + jj)*Ff + f];
        }
        if (tid < 16) {
            float mk = mask[b*Nn + j0 + tid];
            mj[tid] = mk;
            cj[tid*3+0] = coord[(b*Nn+j0+tid)*3+0]*mk;
            cj[tid*3+1] = coord[(b*Nn+j0+tid)*3+1]*mk;
            cj[tid*3+2] = coord[(b*Nn+j0+tid)*3+2]*mk;
        }
        __syncthreads();

        // ---- build m1 hi/lo: thread owns (e = tid/4, 32 k's) ----
        {
            const int e  = tid >> 2;
            const int k0 = (tid & 3) * 32;
            const int ii = e >> 4, jj = e & 15;
            float m2 = mi[ii]*mj[jj];
            float dx = ci[ii*3+0]-cj[jj*3+0];
            float dy = ci[ii*3+1]-cj[jj*3+1];
            float dz = ci[ii*3+2]-cj[jj*3+2];
            float rv = (dx*dx + dy*dy + dz*dz)*m2;
            if ((tid & 3) == 0) m2d[e] = m2;
            const float* Aj = Ajs + jj*129 + k0;
            const float* Bm = Bms + ii*129 + k0;
            #pragma unroll
            for (int c = 0; c < 4; c++) {
                float x[8];
                #pragma unroll
                for (int q = 0; q < 8; q++) {
                    int k = c*8 + q;
                    x[q] = silu_f(Aj[k] + Bm[k] + rv*w1c[k0 + k]);
                }
                bf16 hi[8];
                #pragma unroll
                for (int q = 0; q < 8; q++) hi[q] = __float2bfloat16_rn(x[q]);
                uint4 vh, vl;
                vh.x = (*(unsigned short*)&hi[0]) | ((u32)(*(unsigned short*)&hi[1]) << 16);
                vh.y = (*(unsigned short*)&hi[2]) | ((u32)(*(unsigned short*)&hi[3]) << 16);
                vh.z = (*(unsigned short*)&hi[4]) | ((u32)(*(unsigned short*)&hi[5]) << 16);
                vh.w = (*(unsigned short*)&hi[6]) | ((u32)(*(unsigned short*)&hi[7]) << 16);
                vl.x = pkbf(x[0]-__bfloat162float(hi[0]), x[1]-__bfloat162float(hi[1]));
                vl.y = pkbf(x[2]-__bfloat162float(hi[2]), x[3]-__bfloat162float(hi[3]));
                vl.z = pkbf(x[4]-__bfloat162float(hi[4]), x[5]-__bfloat162float(hi[5]));
                vl.w = pkbf(x[6]-__bfloat162float(hi[6]), x[7]-__bfloat162float(hi[7]));
                int eo = e*LDA + k0 + c*8;
                *(uint4*)(m1hi + eo) = vh;
                *(uint4*)(m1lo + eo) = vl;
            }
        }
        __syncthreads();

        // ---- GEMM2 mma: acc = m1 @ W2 (3-term), 4 persistent accs ----
        wmma::fragment<wmma::accumulator, 16, 16, 16, float> acc[2][2];
        #pragma unroll
        for (int fr = 0; fr < 2; fr++)
            #pragma unroll
            for (int fc = 0; fc < 2; fc++) wmma::fill_fragment(acc[fr][fc], 0.f);
        #pragma unroll
        for (int k0 = 0; k0 < 8; k0++) {
            wmma::fragment<wmma::matrix_a, 16, 16, 16, bf16, wmma::row_major> ah[2], al[2];
            wmma::fragment<wmma::matrix_b, 16, 16, 16, bf16, wmma::row_major> bh[2], bl[2];
            #pragma unroll
            for (int fr = 0; fr < 2; fr++) {
                wmma::load_matrix_sync(ah[fr], m1hi + (r0+16*fr)*LDA + k0*16, LDA);
                wmma::load_matrix_sync(al[fr], m1lo + (r0+16*fr)*LDA + k0*16, LDA);
            }
            #pragma unroll
            for (int fc = 0; fc < 2; fc++) {
                wmma::load_matrix_sync(bh[fc], W2hi + (k0*16)*LDA + c0+16*fc, LDA);
                wmma::load_matrix_sync(bl[fc], W2lo + (k0*16)*LDA + c0+16*fc, LDA);
            }
            #pragma unroll
            for (int fr = 0; fr < 2; fr++)
                #pragma unroll
                for (int fc = 0; fc < 2; fc++) {
                    wmma::mma_sync(acc[fr][fc], ah[fr], bh[fc], acc[fr][fc]);
                    wmma::mma_sync(acc[fr][fc], ah[fr], bl[fc], acc[fr][fc]);
                    wmma::mma_sync(acc[fr][fc], al[fr], bh[fc], acc[fr][fc]);
                }
        }
        __syncthreads();   // all m1hi/lo reads done; m1lo region becomes scratch

        // ---- epilogue 2: m = silu(acc + b2)*m2d ; agg += m ; mbuf <- bf16 m ----
        {
            const int rl = l >> 1, ch = (l & 1) * 8;
            #pragma unroll
            for (int fr = 0; fr < 2; fr++) {
                const int rowg = r0 + 16*fr + rl;
                const float m2v = m2d[rowg];
                #pragma unroll
                for (int fc = 0; fc < 2; fc++) {
                    wmma::store_matrix_sync(scr, acc[fr][fc], SCRLD, wmma::mem_row_major);
                    __syncwarp();
                    float mv[8];
                    #pragma unroll
                    for (int q = 0; q < 8; q++) {
                        int f = c0 + 16*fc + ch + q;
                        float dv = scr[rl*SCRLD + ch + q];
                        mv[q] = silu_f(dv + b2s[f]) * m2v;
                        agg[fr][fc][q] += mv[q];
                    }
                    uint4 vh;
                    vh.x = pkbf(mv[0], mv[1]);
                    vh.y = pkbf(mv[2], mv[3]);
                    vh.z = pkbf(mv[4], mv[5]);
                    vh.w = pkbf(mv[6], mv[7]);
                    *(uint4*)(mbuf + rowg*LDA + c0 + 16*fc + ch) = vh;
                    __syncwarp();
                }
            }
        }
        __syncthreads();   // mbuf complete

        // ---- GEMM3 mma + epilogue 3 (warp-local) ----
        {
            #pragma unroll
            for (int fr = 0; fr < 2; fr++)
                #pragma unroll
                for (int fc = 0; fc < 2; fc++) wmma::fill_fragment(acc[fr][fc], 0.f);
            #pragma unroll
            for (int k0 = 0; k0 < 8; k0++) {
                wmma::fragment<wmma::matrix_a, 16, 16, 16, bf16, wmma::row_major> af[2];
                wmma::fragment<wmma::matrix_b, 16, 16, 16, bf16, wmma::row_major> bfr[2];
                #pragma unroll
                for (int fr = 0; fr < 2; fr++)
                    wmma::load_matrix_sync(af[fr], mbuf + (r0+16*fr)*LDA + k0*16, LDA);
                #pragma unroll
                for (int fc = 0; fc < 2; fc++)
                    wmma::load_matrix_sync(bfr[fc], C1hi + (k0*16)*LDA + c0+16*fc, LDA);
                #pragma unroll
                for (int fr = 0; fr < 2; fr++)
                    #pragma unroll
                    for (int fc = 0; fc < 2; fc++)
                        wmma::mma_sync(acc[fr][fc], af[fr], bfr[fc], acc[fr][fc]);
            }
            const int rl = l >> 1, ch = (l & 1) * 8;
            float pe[2] = {0.f, 0.f};
            #pragma unroll
            for (int fr = 0; fr < 2; fr++) {
                #pragma unroll
                for (int fc = 0; fc < 2; fc++) {
                    wmma::store_matrix_sync(scr, acc[fr][fc], SCRLD, wmma::mem_row_major);
                    __syncwarp();
                    #pragma unroll
                    for (int q = 0; q < 8; q++) {
                        int f = c0 + 16*fc + ch + q;
                        float dv = scr[rl*SCRLD + ch + q];
                        pe[fr] += silu_f(dv + cb1s[f]) * cw2s[f];
                    }
                    __syncwarp();
                }
                pe[fr] += __shfl_xor_sync(0xffffffffu, pe[fr], 1);
                if ((l & 1) == 0) embP[wc*128 + r0 + 16*fr + rl] = pe[fr];
            }
        }
        __syncthreads();   // embP ready

        // ---- trans accumulation (deterministic, 24 threads) ----
        if (tid < 24) {
            int ii = tid/3, d = tid - ii*3;
            float cid = ci[ii*3+d];
            float s = 0.f;
            #pragma unroll
            for (int jj = 0; jj < 16; jj++) {
                int e = ii*16 + jj;
                float m2 = m2d[e];
                float em = embP[e] + embP[128+e] + embP[256+e] + embP[384+e];
                s += (cid - cj[jj*3+d])*m2*em*m2;
            }
            trs[tid] += s;
        }
    }
    __syncthreads();

    // ---- final agg reduction: sum 16 jj-rows (lanes of same parity) ----
    {
        const int ch = (l & 1) * 8;
        #pragma unroll
        for (int fr = 0; fr < 2; fr++) {
            int ii = 2*wr + fr;
            #pragma unroll
            for (int fc = 0; fc < 2; fc++) {
                #pragma unroll
                for (int q = 0; q < 8; q++) {
                    float v = agg[fr][fc][q];
                    v += __shfl_xor_sync(0xffffffffu, v, 2);
                    v += __shfl_xor_sync(0xffffffffu, v, 4);
                    v += __shfl_xor_sync(0xffffffffu, v, 8);
                    v += __shfl_xor_sync(0xffffffffu, v, 16);
                    if (l < 2)
                        g_agg[(b*Nn + i0 + ii)*Ff + c0 + 16*fc + ch + q] = v;
                }
            }
        }
    }
    if (tid < 24) g_trans[(b*Nn + i0 + tid/3)*3 + (tid % 3)] = trs[tid];
}

// ---------------------------------------------------------------------------
__global__ __launch_bounds__(128) void k_node(
    const float* __restrict__ coord, const float* __restrict__ mask,
    const float* __restrict__ nw1, const float* __restrict__ nb1,
    const float* __restrict__ nw2, const float* __restrict__ nb2,
    float* __restrict__ out)
{
    __shared__ float nin[2*Ff];
    __shared__ float t1s[Ff];
    __shared__ float red[Ff];
    const int r = blockIdx.x;
    const int t = threadIdx.x;
    const int b = r >> 9;
    const float mk = mask[r];
    const float hm = g_hm[r*Ff + t];
    nin[t]      = hm * mk;
    nin[Ff + t] = g_agg[r*Ff + t] * mk;
    float s = 0.f;
    for (int q = t; q < Nn; q += 128) s += mask[b*Nn + q];
    red[t] = s;
    __syncthreads();
    for (int off = 64; off >= 1; off >>= 1) {
        if (t < off) red[t] += red[t + off];
        __syncthreads();
    }
    float acc = nb1[t];
    #pragma unroll 8
    for (int k = 0; k < 2*Ff; k++) acc += nin[k]*nw1[k*Ff + t];
    t1s[t] = silu_f(acc);
    __syncthreads();
    float acc2 = nb2[t];
    #pragma unroll 8
    for (int k = 0; k < Ff; k++) acc2 += t1s[k]*nw2[k*Ff + t];
    out[r*Ff + t] = (hm + acc2)*mk;
    if (t < 3) {
        float denom = mk*red[0] + 1e-10f;
        float cm = coord[r*3 + t]*mk;
        out[Bb*Nn*Ff + r*3 + t] = (cm + g_trans[r*3 + t]/denom)*mk;
    }
}

// ---------------------------------------------------------------------------
extern "C" void kernel_launch(void* const* d_in, const int* in_sizes, int n_in,
                              void* d_out, int out_size)
{
    const float* h     = (const float*)d_in[0];
    const float* coord = (const float*)d_in[1];
    const float* mask  = (const float*)d_in[2];
    const float* ew1   = (const float*)d_in[3];
    const float* eb1   = (const float*)d_in[4];
    const float* ew2   = (const float*)d_in[5];
    const float* eb2   = (const float*)d_in[6];
    const float* nw1   = (const float*)d_in[7];
    const float* nb1   = (const float*)d_in[8];
    const float* nw2   = (const float*)d_in[9];
    const float* nb2   = (const float*)d_in[10];
    const float* cw1   = (const float*)d_in[11];
    const float* cb1   = (const float*)d_in[12];
    const float* cw2   = (const float*)d_in[13];

    cudaFuncSetAttribute(k_edge, cudaFuncAttributeMaxDynamicSharedMemorySize, SM_TOTAL);

    k_prep<<<Bb*Nn, 128>>>(h, mask, ew1, eb1);
    k_wprep<<<32, 256>>>(ew2, cw1);
    k_edge<<<Bb*(Nn/8), 512, SM_TOTAL>>>(coord, mask, ew1, eb2, cb1, cw2);
    k_node<<<Bb*Nn, 128>>>(coord, mask, nw1, nb1, nw2, nb2, (float*)d_out);
}

// round 8
// speedup vs baseline: 3.1714x; 1.2398x over previous
#include <cuda_runtime.h>
#include <cuda_bf16.h>

#define Bb 2
#define Nn 512
#define Ff 128
#define LDA 136          /* elements per bf16 tile row (272B) */
#define LDAB 272         /* bytes per row */
#define ROWU4 17

typedef unsigned int u32;
typedef __nv_bfloat16 bf16;

// ------------------------- device scratch (no allocs) -------------------------
__device__ float g_A[Bb*Nn*Ff];
__device__ float g_Bm[Bb*Nn*Ff];
__device__ float g_hm[Bb*Nn*Ff];
__device__ float g_agg[Bb*Nn*Ff];
__device__ float g_trans[Bb*Nn*3];
__device__ bf16  g_w2hi[Ff*Ff];   // [k][f], packed 128 stride
__device__ bf16  g_w2lo[Ff*Ff];
__device__ bf16  g_c1hi[Ff*Ff];

__device__ __forceinline__ float silu_f(float x) { return x / (1.f + __expf(-x)); }
__device__ __forceinline__ u32 pkbf(float a, float b) {
    __nv_bfloat162 t = __floats2bfloat162_rn(a, b);
    return *(u32*)&t;
}
__device__ __forceinline__ u32 cvta_s(const void* p) {
    u32 a; asm("{ .reg .u64 t; cvta.to.shared.u64 t, %1; cvt.u32.u64 %0, t; }" : "=r"(a) : "l"(p));
    return a;
}
__device__ __forceinline__ void ldsm4(u32 &a0, u32 &a1, u32 &a2, u32 &a3, u32 addr) {
    asm volatile("ldmatrix.sync.aligned.m8n8.x4.shared.b16 {%0,%1,%2,%3}, [%4];"
                 : "=r"(a0), "=r"(a1), "=r"(a2), "=r"(a3) : "r"(addr));
}
__device__ __forceinline__ void ldsm4t(u32 &a0, u32 &a1, u32 &a2, u32 &a3, u32 addr) {
    asm volatile("ldmatrix.sync.aligned.m8n8.x4.trans.shared.b16 {%0,%1,%2,%3}, [%4];"
                 : "=r"(a0), "=r"(a1), "=r"(a2), "=r"(a3) : "r"(addr));
}
__device__ __forceinline__ void mma16816(float* c, const u32* a, const u32* b) {
    asm volatile("mma.sync.aligned.m16n8k16.row.col.f32.bf16.bf16.f32 "
                 "{%0,%1,%2,%3}, {%4,%5,%6,%7}, {%8,%9}, {%0,%1,%2,%3};"
                 : "+f"(c[0]), "+f"(c[1]), "+f"(c[2]), "+f"(c[3])
                 : "r"(a[0]), "r"(a[1]), "r"(a[2]), "r"(a[3]), "r"(b[0]), "r"(b[1]));
}

// ------------------------- SMEM layout (bytes) -------------------------
#define SM_M1HI 0                            /* 128*272 = 34816 */
#define SM_M1LO (SM_M1HI + 34816)
#define SM_MBUF (SM_M1LO + 34816)
#define SM_W2HI (SM_MBUF + 34816)
#define SM_W2LO (SM_W2HI + 34816)
#define SM_C1HI (SM_W2LO + 34816)
#define SM_AJS  (SM_C1HI + 34816)            /* 16*129*4 = 8256 */
#define SM_BMS  (SM_AJS + 8256)              /* 8*129*4 = 4128 */
#define SM_W1C  (SM_BMS + 4128)
#define SM_B2S  (SM_W1C + 512)
#define SM_CB1S (SM_B2S + 512)
#define SM_CW2S (SM_CB1S + 512)
#define SM_M2D  (SM_CW2S + 512)
#define SM_EMBP (SM_M2D + 512)               /* 4*128*4 = 2048 */
#define SM_CI   (SM_EMBP + 2048)
#define SM_MI   (SM_CI + 96)
#define SM_CJ   (SM_MI + 32)
#define SM_MJ   (SM_CJ + 192)
#define SM_TRS  (SM_MJ + 64)
#define SM_TOTAL (SM_TRS + 96 + 16)

// ---------------------------------------------------------------------------
__global__ __launch_bounds__(128) void k_prep(
    const float* __restrict__ h, const float* __restrict__ mask,
    const float* __restrict__ ew1, const float* __restrict__ eb1)
{
    __shared__ float hr[Ff];
    const int r = blockIdx.x;
    const int t = threadIdx.x;
    const float mk = mask[r];
    float hv = h[r*Ff + t] * mk;
    hr[t] = hv;
    g_hm[r*Ff + t] = hv;
    __syncthreads();
    float a = 0.f;
    float bm = eb1[t];
    #pragma unroll 8
    for (int k = 0; k < Ff; k++) {
        float hk = hr[k];
        a  += hk * ew1[k*Ff + t];
        bm += hk * ew1[(Ff + k)*Ff + t];
    }
    g_A[r*Ff + t]  = a;
    g_Bm[r*Ff + t] = bm;
}

// ---------------------------------------------------------------------------
__global__ __launch_bounds__(256) void k_wprep(
    const float* __restrict__ ew2, const float* __restrict__ cw1)
{
    for (int idx = blockIdx.x*256 + threadIdx.x; idx < 2*Ff*Ff; idx += gridDim.x*256) {
        int mat = idx >> 14, rem = idx & 16383;
        if (mat == 0) {
            float v = ew2[rem];
            bf16 hi = __float2bfloat16_rn(v);
            g_w2hi[rem] = hi;
            g_w2lo[rem] = __float2bfloat16_rn(v - __bfloat162float(hi));
        } else {
            g_c1hi[rem] = __float2bfloat16_rn(cw1[rem]);
        }
    }
}

// ---------------------------------------------------------------------------
// k_edge: 128 blocks, 512 threads (16 warps; warp grid 4x4 over 128x128)
// raw mma.sync + register epilogues
// ---------------------------------------------------------------------------
__global__ __launch_bounds__(512, 1) void k_edge(
    const float* __restrict__ coord, const float* __restrict__ mask,
    const float* __restrict__ ew1,   const float* __restrict__ eb2,
    const float* __restrict__ cb1,   const float* __restrict__ cw2)
{
    extern __shared__ char smc[];
    bf16*  m1hi = (bf16*)(smc + SM_M1HI);
    bf16*  m1lo = (bf16*)(smc + SM_M1LO);
    bf16*  mbuf = (bf16*)(smc + SM_MBUF);
    float* Ajs  = (float*)(smc + SM_AJS);
    float* Bms  = (float*)(smc + SM_BMS);
    float* w1c  = (float*)(smc + SM_W1C);
    float* b2s  = (float*)(smc + SM_B2S);
    float* cb1s = (float*)(smc + SM_CB1S);
    float* cw2s = (float*)(smc + SM_CW2S);
    float* m2d  = (float*)(smc + SM_M2D);
    float* embP = (float*)(smc + SM_EMBP);
    float* ci   = (float*)(smc + SM_CI);
    float* mi   = (float*)(smc + SM_MI);
    float* cj   = (float*)(smc + SM_CJ);
    float* mj   = (float*)(smc + SM_MJ);
    float* trs  = (float*)(smc + SM_TRS);

    const int tid = threadIdx.x;
    const int w   = tid >> 5, l = tid & 31;
    const int wr  = w >> 2, wc = w & 3;
    const int r0  = wr * 32, c0 = wc * 32;
    const int g   = l >> 2, tg = l & 3;
    const int b   = blockIdx.x >> 6;
    const int i0  = (blockIdx.x & 63) * 8;

    // --- stage weights into SMEM, re-striding 128 -> 136 elems/row ---
    {
        uint4* s1 = (uint4*)(smc + SM_W2HI);
        uint4* s2 = (uint4*)(smc + SM_W2LO);
        uint4* s3 = (uint4*)(smc + SM_C1HI);
        const uint4* d1 = (const uint4*)g_w2hi;
        const uint4* d2 = (const uint4*)g_w2lo;
        const uint4* d3 = (const uint4*)g_c1hi;
        for (int idx = tid; idx < 128*16; idx += 512) {
            int k = idx >> 4, u = idx & 15;
            s1[k*ROWU4 + u] = d1[idx];
            s2[k*ROWU4 + u] = d2[idx];
            s3[k*ROWU4 + u] = d3[idx];
        }
    }
    if (tid < Ff) {
        w1c[tid]  = ew1[2*Ff*Ff + tid];
        b2s[tid]  = eb2[tid];
        cb1s[tid] = cb1[tid];
        cw2s[tid] = cw2[tid];
    }
    if (tid < 8) {
        float mk = mask[b*Nn + i0 + tid];
        mi[tid] = mk;
        ci[tid*3+0] = coord[(b*Nn+i0+tid)*3+0]*mk;
        ci[tid*3+1] = coord[(b*Nn+i0+tid)*3+1]*mk;
        ci[tid*3+2] = coord[(b*Nn+i0+tid)*3+2]*mk;
    }
    if (tid < 24) trs[tid] = 0.f;
    for (int idx = tid; idx < 8*Ff; idx += 512) {
        int ii = idx >> 7, f = idx & 127;
        Bms[ii*129 + f] = g_Bm[(b*Nn + i0 + ii)*Ff + f];
    }
    __syncthreads();

    // --- hoist per-thread epilogue constants into registers ---
    float b2v[4][2], cb1v[4][2], cw2v[4][2];
    #pragma unroll
    for (int nt = 0; nt < 4; nt++) {
        int col = c0 + 8*nt + 2*tg;
        b2v[nt][0]  = b2s[col];    b2v[nt][1]  = b2s[col+1];
        cb1v[nt][0] = cb1s[col];   cb1v[nt][1] = cb1s[col+1];
        cw2v[nt][0] = cw2s[col];   cw2v[nt][1] = cw2s[col+1];
    }

    // --- precompute ldmatrix base addresses ---
    const u32 m1hi_s = cvta_s(m1hi);
    const u32 m1lo_s = cvta_s(m1lo);
    const u32 mbuf_s = cvta_s(mbuf);
    const u32 w2hi_s = cvta_s(smc + SM_W2HI);
    const u32 w2lo_s = cvta_s(smc + SM_W2LO);
    const u32 c1hi_s = cvta_s(smc + SM_C1HI);
    // A pattern: (rowbase + l&15)*272 + (l>>4)*16  [+ k0*32]
    u32 aoffA[2];
    #pragma unroll
    for (int fr = 0; fr < 2; fr++)
        aoffA[fr] = (u32)((r0 + 16*fr + (l & 15))*LDAB + (l >> 4)*16);
    // B pattern: (l&15)*272 + (c0+16*ng)*2 + (l>>4)*16  [+ k0*4352]
    u32 boffB[2];
    #pragma unroll
    for (int ng = 0; ng < 2; ng++)
        boffB[ng] = (u32)((l & 15)*LDAB + (c0 + 16*ng)*2 + (l >> 4)*16);

    float aggp[2][4][2];
    #pragma unroll
    for (int fr = 0; fr < 2; fr++)
        #pragma unroll
        for (int nt = 0; nt < 4; nt++) { aggp[fr][nt][0] = 0.f; aggp[fr][nt][1] = 0.f; }

    for (int jt = 0; jt < Nn/16; jt++) {
        const int j0 = jt*16;
        for (int idx = tid; idx < 16*Ff; idx += 512) {
            int jj = idx >> 7, f = idx & 127;
            Ajs[jj*129 + f] = g_A[(b*Nn + j0 + jj)*Ff + f];
        }
        if (tid < 16) {
            float mk = mask[b*Nn + j0 + tid];
            mj[tid] = mk;
            cj[tid*3+0] = coord[(b*Nn+j0+tid)*3+0]*mk;
            cj[tid*3+1] = coord[(b*Nn+j0+tid)*3+1]*mk;
            cj[tid*3+2] = coord[(b*Nn+j0+tid)*3+2]*mk;
        }
        __syncthreads();

        // ---- build m1 hi/lo: thread owns (e = tid/4, 32 k's) ----
        {
            const int e  = tid >> 2;
            const int k0 = (tid & 3) * 32;
            const int ii = e >> 4, jj = e & 15;
            float m2 = mi[ii]*mj[jj];
            float dx = ci[ii*3+0]-cj[jj*3+0];
            float dy = ci[ii*3+1]-cj[jj*3+1];
            float dz = ci[ii*3+2]-cj[jj*3+2];
            float rv = (dx*dx + dy*dy + dz*dz)*m2;
            if ((tid & 3) == 0) m2d[e] = m2;
            const float* Aj = Ajs + jj*129 + k0;
            const float* Bm = Bms + ii*129 + k0;
            #pragma unroll
            for (int c = 0; c < 4; c++) {
                float x[8];
                #pragma unroll
                for (int q = 0; q < 8; q++) {
                    int k = c*8 + q;
                    x[q] = silu_f(Aj[k] + Bm[k] + rv*w1c[k0 + k]);
                }
                bf16 hi[8];
                #pragma unroll
                for (int q = 0; q < 8; q++) hi[q] = __float2bfloat16_rn(x[q]);
                uint4 vh, vl;
                vh.x = (*(unsigned short*)&hi[0]) | ((u32)(*(unsigned short*)&hi[1]) << 16);
                vh.y = (*(unsigned short*)&hi[2]) | ((u32)(*(unsigned short*)&hi[3]) << 16);
                vh.z = (*(unsigned short*)&hi[4]) | ((u32)(*(unsigned short*)&hi[5]) << 16);
                vh.w = (*(unsigned short*)&hi[6]) | ((u32)(*(unsigned short*)&hi[7]) << 16);
                vl.x = pkbf(x[0]-__bfloat162float(hi[0]), x[1]-__bfloat162float(hi[1]));
                vl.y = pkbf(x[2]-__bfloat162float(hi[2]), x[3]-__bfloat162float(hi[3]));
                vl.z = pkbf(x[4]-__bfloat162float(hi[4]), x[5]-__bfloat162float(hi[5]));
                vl.w = pkbf(x[6]-__bfloat162float(hi[6]), x[7]-__bfloat162float(hi[7]));
                int eo = e*LDA + k0 + c*8;
                *(uint4*)(m1hi + eo) = vh;
                *(uint4*)(m1lo + eo) = vl;
            }
        }
        __syncthreads();

        // ---- GEMM2: acc = m1 @ W2 (3-term hi/lo split) ----
        float acc[2][4][4];
        #pragma unroll
        for (int fr = 0; fr < 2; fr++)
            #pragma unroll
            for (int nt = 0; nt < 4; nt++)
                #pragma unroll
                for (int q = 0; q < 4; q++) acc[fr][nt][q] = 0.f;
        #pragma unroll
        for (int k0 = 0; k0 < 8; k0++) {
            u32 ah[2][4], al[2][4], bh[4][2], bl[4][2];
            #pragma unroll
            for (int fr = 0; fr < 2; fr++) {
                ldsm4(ah[fr][0], ah[fr][1], ah[fr][2], ah[fr][3], m1hi_s + aoffA[fr] + k0*32);
                ldsm4(al[fr][0], al[fr][1], al[fr][2], al[fr][3], m1lo_s + aoffA[fr] + k0*32);
            }
            #pragma unroll
            for (int ng = 0; ng < 2; ng++) {
                ldsm4t(bh[2*ng][0], bh[2*ng][1], bh[2*ng+1][0], bh[2*ng+1][1],
                       w2hi_s + boffB[ng] + k0*16*LDAB);
                ldsm4t(bl[2*ng][0], bl[2*ng][1], bl[2*ng+1][0], bl[2*ng+1][1],
                       w2lo_s + boffB[ng] + k0*16*LDAB);
            }
            #pragma unroll
            for (int fr = 0; fr < 2; fr++)
                #pragma unroll
                for (int nt = 0; nt < 4; nt++) {
                    mma16816(acc[fr][nt], ah[fr], bh[nt]);
                    mma16816(acc[fr][nt], ah[fr], bl[nt]);
                    mma16816(acc[fr][nt], al[fr], bh[nt]);
                }
        }

        // ---- epilogue 2 (registers): m = silu(acc+b2)*m2d ; agg+= ; mbuf<-bf16 ----
        #pragma unroll
        for (int fr = 0; fr < 2; fr++) {
            const int rlo = r0 + 16*fr + g;
            const int rhi = rlo + 8;
            const float m2lo = m2d[rlo];
            const float m2hi = m2d[rhi];
            #pragma unroll
            for (int nt = 0; nt < 4; nt++) {
                int col = c0 + 8*nt + 2*tg;
                float v0 = silu_f(acc[fr][nt][0] + b2v[nt][0]) * m2lo;
                float v1 = silu_f(acc[fr][nt][1] + b2v[nt][1]) * m2lo;
                float v2 = silu_f(acc[fr][nt][2] + b2v[nt][0]) * m2hi;
                float v3 = silu_f(acc[fr][nt][3] + b2v[nt][1]) * m2hi;
                aggp[fr][nt][0] += v0 + v2;
                aggp[fr][nt][1] += v1 + v3;
                *(u32*)(mbuf + rlo*LDA + col) = pkbf(v0, v1);
                *(u32*)(mbuf + rhi*LDA + col) = pkbf(v2, v3);
            }
        }
        __syncthreads();   // mbuf complete (all warps)

        // ---- GEMM3: acc3 = m @ coord_w1 (single bf16 term) ----
        float acc3[2][4][4];
        #pragma unroll
        for (int fr = 0; fr < 2; fr++)
            #pragma unroll
            for (int nt = 0; nt < 4; nt++)
                #pragma unroll
                for (int q = 0; q < 4; q++) acc3[fr][nt][q] = 0.f;
        #pragma unroll
        for (int k0 = 0; k0 < 8; k0++) {
            u32 af[2][4], bc[4][2];
            #pragma unroll
            for (int fr = 0; fr < 2; fr++)
                ldsm4(af[fr][0], af[fr][1], af[fr][2], af[fr][3], mbuf_s + aoffA[fr] + k0*32);
            #pragma unroll
            for (int ng = 0; ng < 2; ng++)
                ldsm4t(bc[2*ng][0], bc[2*ng][1], bc[2*ng+1][0], bc[2*ng+1][1],
                       c1hi_s + boffB[ng] + k0*16*LDAB);
            #pragma unroll
            for (int fr = 0; fr < 2; fr++)
                #pragma unroll
                for (int nt = 0; nt < 4; nt++)
                    mma16816(acc3[fr][nt], af[fr], bc[nt]);
        }

        // ---- epilogue 3 (registers): embed partials ----
        #pragma unroll
        for (int fr = 0; fr < 2; fr++) {
            float plo = 0.f, phi = 0.f;
            #pragma unroll
            for (int nt = 0; nt < 4; nt++) {
                plo += silu_f(acc3[fr][nt][0] + cb1v[nt][0]) * cw2v[nt][0];
                plo += silu_f(acc3[fr][nt][1] + cb1v[nt][1]) * cw2v[nt][1];
                phi += silu_f(acc3[fr][nt][2] + cb1v[nt][0]) * cw2v[nt][0];
                phi += silu_f(acc3[fr][nt][3] + cb1v[nt][1]) * cw2v[nt][1];
            }
            plo += __shfl_xor_sync(0xffffffffu, plo, 1);
            plo += __shfl_xor_sync(0xffffffffu, plo, 2);
            phi += __shfl_xor_sync(0xffffffffu, phi, 1);
            phi += __shfl_xor_sync(0xffffffffu, phi, 2);
            if (tg == 0) {
                embP[wc*128 + r0 + 16*fr + g]     = plo;
                embP[wc*128 + r0 + 16*fr + g + 8] = phi;
            }
        }
        __syncthreads();   // embP ready

        // ---- trans accumulation (deterministic, 24 threads) ----
        if (tid < 24) {
            int ii = tid/3, d = tid - ii*3;
            float cid = ci[ii*3+d];
            float s = 0.f;
            #pragma unroll
            for (int jj = 0; jj < 16; jj++) {
                int e = ii*16 + jj;
                float m2 = m2d[e];
                float em = embP[e] + embP[128+e] + embP[256+e] + embP[384+e];
                s += (cid - cj[jj*3+d])*m2*em*m2;
            }
            trs[tid] += s;
        }
        __syncthreads();   // next iteration may overwrite Ajs/cj/mj/m1/embP
    }

    // ---- final agg reduction: sum over j-rows (lanes g=0..7 via xor 4,8,16) ----
    #pragma unroll
    for (int fr = 0; fr < 2; fr++) {
        #pragma unroll
        for (int nt = 0; nt < 4; nt++) {
            #pragma unroll
            for (int q = 0; q < 2; q++) {
                float v = aggp[fr][nt][q];
                v += __shfl_xor_sync(0xffffffffu, v, 4);
                v += __shfl_xor_sync(0xffffffffu, v, 8);
                v += __shfl_xor_sync(0xffffffffu, v, 16);
                if (l < 4)
                    g_agg[(b*Nn + i0 + 2*wr + fr)*Ff + c0 + 8*nt + 2*tg + q] = v;
            }
        }
    }
    if (tid < 24) g_trans[(b*Nn + i0 + tid/3)*3 + (tid % 3)] = trs[tid];
}

// ---------------------------------------------------------------------------
__global__ __launch_bounds__(128) void k_node(
    const float* __restrict__ coord, const float* __restrict__ mask,
    const float* __restrict__ nw1, const float* __restrict__ nb1,
    const float* __restrict__ nw2, const float* __restrict__ nb2,
    float* __restrict__ out)
{
    __shared__ float nin[2*Ff];
    __shared__ float t1s[Ff];
    __shared__ float red[Ff];
    const int r = blockIdx.x;
    const int t = threadIdx.x;
    const int b = r >> 9;
    const float mk = mask[r];
    const float hm = g_hm[r*Ff + t];
    nin[t]      = hm * mk;
    nin[Ff + t] = g_agg[r*Ff + t] * mk;
    float s = 0.f;
    for (int q = t; q < Nn; q += 128) s += mask[b*Nn + q];
    red[t] = s;
    __syncthreads();
    for (int off = 64; off >= 1; off >>= 1) {
        if (t < off) red[t] += red[t + off];
        __syncthreads();
    }
    float acc = nb1[t];
    #pragma unroll 8
    for (int k = 0; k < 2*Ff; k++) acc += nin[k]*nw1[k*Ff + t];
    t1s[t] = silu_f(acc);
    __syncthreads();
    float acc2 = nb2[t];
    #pragma unroll 8
    for (int k = 0; k < Ff; k++) acc2 += t1s[k]*nw2[k*Ff + t];
    out[r*Ff + t] = (hm + acc2)*mk;
    if (t < 3) {
        float denom = mk*red[0] + 1e-10f;
        float cm = coord[r*3 + t]*mk;
        out[Bb*Nn*Ff + r*3 + t] = (cm + g_trans[r*3 + t]/denom)*mk;
    }
}

// ---------------------------------------------------------------------------
extern "C" void kernel_launch(void* const* d_in, const int* in_sizes, int n_in,
                              void* d_out, int out_size)
{
    const float* h     = (const float*)d_in[0];
    const float* coord = (const float*)d_in[1];
    const float* mask  = (const float*)d_in[2];
    const float* ew1   = (const float*)d_in[3];
    const float* eb1   = (const float*)d_in[4];
    const float* ew2   = (const float*)d_in[5];
    const float* eb2   = (const float*)d_in[6];
    const float* nw1   = (const float*)d_in[7];
    const float* nb1   = (const float*)d_in[8];
    const float* nw2   = (const float*)d_in[9];
    const float* nb2   = (const float*)d_in[10];
    const float* cw1   = (const float*)d_in[11];
    const float* cb1   = (const float*)d_in[12];
    const float* cw2   = (const float*)d_in[13];

    cudaFuncSetAttribute(k_edge, cudaFuncAttributeMaxDynamicSharedMemorySize, SM_TOTAL);

    k_prep<<<Bb*Nn, 128>>>(h, mask, ew1, eb1);
    k_wprep<<<32, 256>>>(ew2, cw1);
    k_edge<<<Bb*(Nn/8), 512, SM_TOTAL>>>(coord, mask, ew1, eb2, cb1, cw2);
    k_node<<<Bb*Nn, 128>>>(coord, mask, nw1, nb1, nw2, nb2, (float*)d_out);
}

// round 9
// speedup vs baseline: 3.2164x; 1.0142x over previous
#include <cuda_runtime.h>
#include <cuda_bf16.h>

#define Bb 2
#define Nn 512
#define Ff 128
#define LDA 136          /* elements per bf16 tile row (272B) */
#define LDAB 272
#define ROWU4 17

typedef unsigned int u32;
typedef unsigned long long u64;
typedef __nv_bfloat16 bf16;

// ------------------------- device scratch (no allocs) -------------------------
__device__ float g_A[Bb*Nn*Ff];
__device__ float g_Bm[Bb*Nn*Ff];
__device__ float g_hm[Bb*Nn*Ff];
__device__ float g_agg[Bb*Nn*Ff];
__device__ float g_trans[Bb*Nn*3];
__device__ bf16  g_w2hi[Ff*Ff];
__device__ bf16  g_w2lo[Ff*Ff];
__device__ bf16  g_c1hi[Ff*Ff];

__device__ __forceinline__ float silu_f(float x) { return x / (1.f + __expf(-x)); }
__device__ __forceinline__ u32 pkbf(float a, float b) {
    __nv_bfloat162 t = __floats2bfloat162_rn(a, b);
    return *(u32*)&t;
}
__device__ __forceinline__ u32 cvta_s(const void* p) {
    u32 a; asm("{ .reg .u64 t; cvta.to.shared.u64 t, %1; cvt.u32.u64 %0, t; }" : "=r"(a) : "l"(p));
    return a;
}
__device__ __forceinline__ void ldsm4(u32 &a0, u32 &a1, u32 &a2, u32 &a3, u32 addr) {
    asm volatile("ldmatrix.sync.aligned.m8n8.x4.shared.b16 {%0,%1,%2,%3}, [%4];"
                 : "=r"(a0), "=r"(a1), "=r"(a2), "=r"(a3) : "r"(addr));
}
__device__ __forceinline__ void ldsm4t(u32 &a0, u32 &a1, u32 &a2, u32 &a3, u32 addr) {
    asm volatile("ldmatrix.sync.aligned.m8n8.x4.trans.shared.b16 {%0,%1,%2,%3}, [%4];"
                 : "=r"(a0), "=r"(a1), "=r"(a2), "=r"(a3) : "r"(addr));
}
__device__ __forceinline__ void mma16816(float* c, const u32* a, const u32* b) {
    asm volatile("mma.sync.aligned.m16n8k16.row.col.f32.bf16.bf16.f32 "
                 "{%0,%1,%2,%3}, {%4,%5,%6,%7}, {%8,%9}, {%0,%1,%2,%3};"
                 : "+f"(c[0]), "+f"(c[1]), "+f"(c[2]), "+f"(c[3])
                 : "r"(a[0]), "r"(a[1]), "r"(a[2]), "r"(a[3]), "r"(b[0]), "r"(b[1]));
}
__device__ __forceinline__ u64 pack2(float x) {
    u64 r; asm("mov.b64 %0, {%1, %1};" : "=l"(r) : "f"(x)); return r;
}
__device__ __forceinline__ u64 pack2d(float a, float b) {
    u64 r; asm("mov.b64 %0, {%1, %2};" : "=l"(r) : "f"(a), "f"(b)); return r;
}
__device__ __forceinline__ void ffma2(u64 &d, u64 a, u64 b) {
    asm("fma.rn.f32x2 %0, %1, %2, %0;" : "+l"(d) : "l"(a), "l"(b));
}
__device__ __forceinline__ float2 unpack2(u64 v) {
    float2 r; asm("mov.b64 {%0, %1}, %2;" : "=f"(r.x), "=f"(r.y) : "l"(v)); return r;
}
#define GBAR(id) asm volatile("bar.sync %0, 128;" :: "r"(id) : "memory")

// ------------------------- SMEM layout (bytes) -------------------------
#define SM_M1HI 0                            /* 128*272 = 34816 */
#define SM_M1LO (SM_M1HI + 34816)
#define SM_MBUF (SM_M1LO + 34816)
#define SM_W2HI (SM_MBUF + 34816)
#define SM_W2LO (SM_W2HI + 34816)
#define SM_C1HI (SM_W2LO + 34816)
#define SM_BMS  (SM_C1HI + 34816)            /* 8*129*4 = 4128 */
#define SM_W1C  (SM_BMS + 4128)
#define SM_B2S  (SM_W1C + 512)
#define SM_CB1S (SM_B2S + 512)
#define SM_CW2S (SM_CB1S + 512)
#define SM_M2D  (SM_CW2S + 512)
#define SM_EMBP (SM_M2D + 512)               /* 4*128*4 = 2048 */
#define SM_CI   (SM_EMBP + 2048)
#define SM_MI   (SM_CI + 96)
#define SM_TOTAL (SM_MI + 32 + 16)

// ---------------------------------------------------------------------------
// k_prep: 8 nodes/block, FFMA2; hm = h*mask ; A = hm@W1a ; Bm = hm@W1b + b1
// grid = 128, 256 threads
// ---------------------------------------------------------------------------
__global__ __launch_bounds__(256) void k_prep(
    const float* __restrict__ h, const float* __restrict__ mask,
    const float* __restrict__ ew1, const float* __restrict__ eb1)
{
    __shared__ float hrs[8][Ff];
    const int t  = threadIdx.x;
    const int r0 = blockIdx.x * 8;
    for (int idx = t; idx < 8*Ff; idx += 256) {
        int nd = idx >> 7, f = idx & 127;
        float hv = h[(r0+nd)*Ff + f] * mask[r0+nd];
        hrs[nd][f] = hv;
        g_hm[(r0+nd)*Ff + f] = hv;
    }
    __syncthreads();
    const int f2 = (t & 63) * 2;
    const int nd0 = (t >> 6) * 2;
    u64 accA0 = 0, accA1 = 0, accB0, accB1;
    {
        u64 bb = *(const u64*)(&((const float*)eb1)[f2]);
        accB0 = bb; accB1 = bb;
    }
    #pragma unroll 4
    for (int k = 0; k < Ff; k++) {
        u64 wa = *(const u64*)(ew1 + k*Ff + f2);
        u64 wb = *(const u64*)(ew1 + (Ff+k)*Ff + f2);
        u64 a0 = pack2(hrs[nd0][k]);
        u64 a1 = pack2(hrs[nd0+1][k]);
        ffma2(accA0, a0, wa); ffma2(accA1, a1, wa);
        ffma2(accB0, a0, wb); ffma2(accB1, a1, wb);
    }
    *(u64*)(g_A  + (r0+nd0  )*Ff + f2) = accA0;
    *(u64*)(g_A  + (r0+nd0+1)*Ff + f2) = accA1;
    *(u64*)(g_Bm + (r0+nd0  )*Ff + f2) = accB0;
    *(u64*)(g_Bm + (r0+nd0+1)*Ff + f2) = accB1;
}

// ---------------------------------------------------------------------------
__global__ __launch_bounds__(256) void k_wprep(
    const float* __restrict__ ew2, const float* __restrict__ cw1)
{
    for (int idx = blockIdx.x*256 + threadIdx.x; idx < 2*Ff*Ff; idx += gridDim.x*256) {
        int mat = idx >> 14, rem = idx & 16383;
        if (mat == 0) {
            float v = ew2[rem];
            bf16 hi = __float2bfloat16_rn(v);
            g_w2hi[rem] = hi;
            g_w2lo[rem] = __float2bfloat16_rn(v - __bfloat162float(hi));
        } else {
            g_c1hi[rem] = __float2bfloat16_rn(cw1[rem]);
        }
    }
}

// ---------------------------------------------------------------------------
// k_edge: 128 blocks, 512 threads; 4 free-running row-groups of 128 threads,
// synced by named barriers only. Raw mma.sync + register epilogues.
// ---------------------------------------------------------------------------
__global__ __launch_bounds__(512, 1) void k_edge(
    const float* __restrict__ coord, const float* __restrict__ mask,
    const float* __restrict__ ew1,   const float* __restrict__ eb2,
    const float* __restrict__ cb1,   const float* __restrict__ cw2)
{
    extern __shared__ char smc[];
    bf16*  m1hi = (bf16*)(smc + SM_M1HI);
    bf16*  m1lo = (bf16*)(smc + SM_M1LO);
    bf16*  mbuf = (bf16*)(smc + SM_MBUF);
    float* Bms  = (float*)(smc + SM_BMS);
    float* w1c  = (float*)(smc + SM_W1C);
    float* b2s  = (float*)(smc + SM_B2S);
    float* cb1s = (float*)(smc + SM_CB1S);
    float* cw2s = (float*)(smc + SM_CW2S);
    float* m2d  = (float*)(smc + SM_M2D);
    float* embP = (float*)(smc + SM_EMBP);
    float* ci   = (float*)(smc + SM_CI);
    float* mi   = (float*)(smc + SM_MI);

    const int tid = threadIdx.x;
    const int l   = tid & 31;
    const int wr  = tid >> 7;            // row-group 0..3
    const int wc  = (tid >> 5) & 3;      // column warp within group
    const int lt  = tid & 127;           // thread within group
    const int r0  = wr * 32, c0 = wc * 32;
    const int g   = l >> 2, tg = l & 3;
    const int b   = blockIdx.x >> 6;
    const int i0  = (blockIdx.x & 63) * 8;
    const int barid = wr + 1;

    // --- prologue: stage weights + per-block constants ---
    {
        uint4* s1 = (uint4*)(smc + SM_W2HI);
        uint4* s2 = (uint4*)(smc + SM_W2LO);
        uint4* s3 = (uint4*)(smc + SM_C1HI);
        const uint4* d1 = (const uint4*)g_w2hi;
        const uint4* d2 = (const uint4*)g_w2lo;
        const uint4* d3 = (const uint4*)g_c1hi;
        for (int idx = tid; idx < 128*16; idx += 512) {
            int k = idx >> 4, u = idx & 15;
            s1[k*ROWU4 + u] = d1[idx];
            s2[k*ROWU4 + u] = d2[idx];
            s3[k*ROWU4 + u] = d3[idx];
        }
    }
    if (tid < Ff) {
        w1c[tid]  = ew1[2*Ff*Ff + tid];
        b2s[tid]  = eb2[tid];
        cb1s[tid] = cb1[tid];
        cw2s[tid] = cw2[tid];
    }
    if (tid < 8) {
        float mk = mask[b*Nn + i0 + tid];
        mi[tid] = mk;
        ci[tid*3+0] = coord[(b*Nn+i0+tid)*3+0]*mk;
        ci[tid*3+1] = coord[(b*Nn+i0+tid)*3+1]*mk;
        ci[tid*3+2] = coord[(b*Nn+i0+tid)*3+2]*mk;
    }
    for (int idx = tid; idx < 8*Ff; idx += 512) {
        int ii = idx >> 7, f = idx & 127;
        Bms[ii*129 + f] = g_Bm[(b*Nn + i0 + ii)*Ff + f];
    }
    __syncthreads();

    // --- per-thread hoisted epilogue constants ---
    float b2v[4][2], cb1v[4][2], cw2v[4][2];
    #pragma unroll
    for (int nt = 0; nt < 4; nt++) {
        int col = c0 + 8*nt + 2*tg;
        b2v[nt][0]  = b2s[col];    b2v[nt][1]  = b2s[col+1];
        cb1v[nt][0] = cb1s[col];   cb1v[nt][1] = cb1s[col+1];
        cw2v[nt][0] = cw2s[col];   cw2v[nt][1] = cw2s[col+1];
    }

    const u32 m1hi_s = cvta_s(m1hi);
    const u32 m1lo_s = cvta_s(m1lo);
    const u32 mbuf_s = cvta_s(mbuf);
    const u32 w2hi_s = cvta_s(smc + SM_W2HI);
    const u32 w2lo_s = cvta_s(smc + SM_W2LO);
    const u32 c1hi_s = cvta_s(smc + SM_C1HI);
    u32 aoffA[2];
    #pragma unroll
    for (int fr = 0; fr < 2; fr++)
        aoffA[fr] = (u32)((r0 + 16*fr + (l & 15))*LDAB + (l >> 4)*16);
    u32 boffB[2];
    #pragma unroll
    for (int ng = 0; ng < 2; ng++)
        boffB[ng] = (u32)((l & 15)*LDAB + (c0 + 16*ng)*2 + (l >> 4)*16);

    // build-phase constants (this thread's edge row + k-slice)
    const int be  = r0 + (lt >> 2);         // edge row 0..127 (within group rows)
    const int bk0 = (lt & 3) * 32;          // k-slice base
    const int bii = be >> 4, bjj = be & 15; // i-offset, j-offset

    // trans accumulators (6 threads per group: lt<6)
    const int t_il = lt / 3, t_d = lt - t_il*3;   // valid when lt<6
    float trs_reg = 0.f;

    float aggp[2][4][2];
    #pragma unroll
    for (int fr = 0; fr < 2; fr++)
        #pragma unroll
        for (int nt = 0; nt < 4; nt++) { aggp[fr][nt][0] = 0.f; aggp[fr][nt][1] = 0.f; }

    for (int jt = 0; jt < Nn/16; jt++) {
        const int j0 = jt*16;
        GBAR(barid);   // m1/m2d free for this group (prev GEMM2/trans done)

        // ---- build m1 hi/lo for this group's 32 rows ----
        {
            const int jn = b*Nn + j0 + bjj;
            const float mkj = mask[jn];
            float m2 = mi[bii]*mkj;
            float cjx = coord[jn*3+0]*mkj;
            float cjy = coord[jn*3+1]*mkj;
            float cjz = coord[jn*3+2]*mkj;
            float dx = ci[bii*3+0]-cjx;
            float dy = ci[bii*3+1]-cjy;
            float dz = ci[bii*3+2]-cjz;
            float rv = (dx*dx + dy*dy + dz*dz)*m2;
            if ((lt & 3) == 0) m2d[be] = m2;
            const float* Aj = g_A + jn*Ff + bk0;
            const float* Bm = Bms + bii*129 + bk0;
            #pragma unroll
            for (int c = 0; c < 4; c++) {
                float4 av = *(const float4*)(Aj + c*8);
                float4 av2 = *(const float4*)(Aj + c*8 + 4);
                float x[8];
                x[0] = silu_f(av.x  + Bm[c*8+0] + rv*w1c[bk0+c*8+0]);
                x[1] = silu_f(av.y  + Bm[c*8+1] + rv*w1c[bk0+c*8+1]);
                x[2] = silu_f(av.z  + Bm[c*8+2] + rv*w1c[bk0+c*8+2]);
                x[3] = silu_f(av.w  + Bm[c*8+3] + rv*w1c[bk0+c*8+3]);
                x[4] = silu_f(av2.x + Bm[c*8+4] + rv*w1c[bk0+c*8+4]);
                x[5] = silu_f(av2.y + Bm[c*8+5] + rv*w1c[bk0+c*8+5]);
                x[6] = silu_f(av2.z + Bm[c*8+6] + rv*w1c[bk0+c*8+6]);
                x[7] = silu_f(av2.w + Bm[c*8+7] + rv*w1c[bk0+c*8+7]);
                bf16 hi[8];
                #pragma unroll
                for (int q = 0; q < 8; q++) hi[q] = __float2bfloat16_rn(x[q]);
                uint4 vh, vl;
                vh.x = (*(unsigned short*)&hi[0]) | ((u32)(*(unsigned short*)&hi[1]) << 16);
                vh.y = (*(unsigned short*)&hi[2]) | ((u32)(*(unsigned short*)&hi[3]) << 16);
                vh.z = (*(unsigned short*)&hi[4]) | ((u32)(*(unsigned short*)&hi[5]) << 16);
                vh.w = (*(unsigned short*)&hi[6]) | ((u32)(*(unsigned short*)&hi[7]) << 16);
                vl.x = pkbf(x[0]-__bfloat162float(hi[0]), x[1]-__bfloat162float(hi[1]));
                vl.y = pkbf(x[2]-__bfloat162float(hi[2]), x[3]-__bfloat162float(hi[3]));
                vl.z = pkbf(x[4]-__bfloat162float(hi[4]), x[5]-__bfloat162float(hi[5]));
                vl.w = pkbf(x[6]-__bfloat162float(hi[6]), x[7]-__bfloat162float(hi[7]));
                int eo = be*LDA + bk0 + c*8;
                *(uint4*)(m1hi + eo) = vh;
                *(uint4*)(m1lo + eo) = vl;
            }
        }
        GBAR(barid);   // m1(t) + m2d(t) ready for group

        // ---- GEMM2: acc = m1 @ W2 (3-term hi/lo split) ----
        float acc[2][4][4];
        #pragma unroll
        for (int fr = 0; fr < 2; fr++)
            #pragma unroll
            for (int nt = 0; nt < 4; nt++)
                #pragma unroll
                for (int q = 0; q < 4; q++) acc[fr][nt][q] = 0.f;
        #pragma unroll
        for (int k0 = 0; k0 < 8; k0++) {
            u32 ah[2][4], al[2][4], bh[4][2], bl[4][2];
            #pragma unroll
            for (int fr = 0; fr < 2; fr++) {
                ldsm4(ah[fr][0], ah[fr][1], ah[fr][2], ah[fr][3], m1hi_s + aoffA[fr] + k0*32);
                ldsm4(al[fr][0], al[fr][1], al[fr][2], al[fr][3], m1lo_s + aoffA[fr] + k0*32);
            }
            #pragma unroll
            for (int ng = 0; ng < 2; ng++) {
                ldsm4t(bh[2*ng][0], bh[2*ng][1], bh[2*ng+1][0], bh[2*ng+1][1],
                       w2hi_s + boffB[ng] + k0*16*LDAB);
                ldsm4t(bl[2*ng][0], bl[2*ng][1], bl[2*ng+1][0], bl[2*ng+1][1],
                       w2lo_s + boffB[ng] + k0*16*LDAB);
            }
            #pragma unroll
            for (int fr = 0; fr < 2; fr++)
                #pragma unroll
                for (int nt = 0; nt < 4; nt++) {
                    mma16816(acc[fr][nt], ah[fr], bh[nt]);
                    mma16816(acc[fr][nt], ah[fr], bl[nt]);
                    mma16816(acc[fr][nt], al[fr], bh[nt]);
                }
        }

        // ---- epilogue 2 (registers) ----
        #pragma unroll
        for (int fr = 0; fr < 2; fr++) {
            const int rlo = r0 + 16*fr + g;
            const int rhi = rlo + 8;
            const float m2lo = m2d[rlo];
            const float m2hi = m2d[rhi];
            #pragma unroll
            for (int nt = 0; nt < 4; nt++) {
                int col = c0 + 8*nt + 2*tg;
                float v0 = silu_f(acc[fr][nt][0] + b2v[nt][0]) * m2lo;
                float v1 = silu_f(acc[fr][nt][1] + b2v[nt][1]) * m2lo;
                float v2 = silu_f(acc[fr][nt][2] + b2v[nt][0]) * m2hi;
                float v3 = silu_f(acc[fr][nt][3] + b2v[nt][1]) * m2hi;
                aggp[fr][nt][0] += v0 + v2;
                aggp[fr][nt][1] += v1 + v3;
                *(u32*)(mbuf + rlo*LDA + col) = pkbf(v0, v1);
                *(u32*)(mbuf + rhi*LDA + col) = pkbf(v2, v3);
            }
        }
        GBAR(barid);   // mbuf(t) rows ready for group

        // ---- GEMM3: acc3 = m @ coord_w1 ----
        float acc3[2][4][4];
        #pragma unroll
        for (int fr = 0; fr < 2; fr++)
            #pragma unroll
            for (int nt = 0; nt < 4; nt++)
                #pragma unroll
                for (int q = 0; q < 4; q++) acc3[fr][nt][q] = 0.f;
        #pragma unroll
        for (int k0 = 0; k0 < 8; k0++) {
            u32 af[2][4], bc[4][2];
            #pragma unroll
            for (int fr = 0; fr < 2; fr++)
                ldsm4(af[fr][0], af[fr][1], af[fr][2], af[fr][3], mbuf_s + aoffA[fr] + k0*32);
            #pragma unroll
            for (int ng = 0; ng < 2; ng++)
                ldsm4t(bc[2*ng][0], bc[2*ng][1], bc[2*ng+1][0], bc[2*ng+1][1],
                       c1hi_s + boffB[ng] + k0*16*LDAB);
            #pragma unroll
            for (int fr = 0; fr < 2; fr++)
                #pragma unroll
                for (int nt = 0; nt < 4; nt++)
                    mma16816(acc3[fr][nt], af[fr], bc[nt]);
        }

        // ---- epilogue 3 (registers): embed partials ----
        #pragma unroll
        for (int fr = 0; fr < 2; fr++) {
            float plo = 0.f, phi = 0.f;
            #pragma unroll
            for (int nt = 0; nt < 4; nt++) {
                plo += silu_f(acc3[fr][nt][0] + cb1v[nt][0]) * cw2v[nt][0];
                plo += silu_f(acc3[fr][nt][1] + cb1v[nt][1]) * cw2v[nt][1];
                phi += silu_f(acc3[fr][nt][2] + cb1v[nt][0]) * cw2v[nt][0];
                phi += silu_f(acc3[fr][nt][3] + cb1v[nt][1]) * cw2v[nt][1];
            }
            plo += __shfl_xor_sync(0xffffffffu, plo, 1);
            plo += __shfl_xor_sync(0xffffffffu, plo, 2);
            phi += __shfl_xor_sync(0xffffffffu, phi, 1);
            phi += __shfl_xor_sync(0xffffffffu, phi, 2);
            if (tg == 0) {
                embP[wc*128 + r0 + 16*fr + g]     = plo;
                embP[wc*128 + r0 + 16*fr + g + 8] = phi;
            }
        }
        GBAR(barid);   // embP(t) rows ready for group

        // ---- trans accumulation (6 threads/group, deterministic) ----
        if (lt < 6) {
            const int ii = 2*wr + t_il;
            const float cid = ci[ii*3 + t_d];
            float s = 0.f;
            #pragma unroll
            for (int jj = 0; jj < 16; jj++) {
                int e = ii*16 + jj;
                int jn = b*Nn + j0 + jj;
                float m2 = m2d[e];
                float cjd = coord[jn*3 + t_d]*mask[jn];
                float em = embP[e] + embP[128+e] + embP[256+e] + embP[384+e];
                s += (cid - cjd)*m2*em*m2;
            }
            trs_reg += s;
        }
    }

    // ---- final agg reduction ----
    #pragma unroll
    for (int fr = 0; fr < 2; fr++) {
        #pragma unroll
        for (int nt = 0; nt < 4; nt++) {
            #pragma unroll
            for (int q = 0; q < 2; q++) {
                float v = aggp[fr][nt][q];
                v += __shfl_xor_sync(0xffffffffu, v, 4);
                v += __shfl_xor_sync(0xffffffffu, v, 8);
                v += __shfl_xor_sync(0xffffffffu, v, 16);
                if (l < 4)
                    g_agg[(b*Nn + i0 + 2*wr + fr)*Ff + c0 + 8*nt + 2*tg + q] = v;
            }
        }
    }
    if (lt < 6)
        g_trans[(b*Nn + i0 + 2*wr + t_il)*3 + t_d] = trs_reg;
}

// ---------------------------------------------------------------------------
// k_node: 8 nodes/block, FFMA2; grid = 128 blocks, 256 threads
// ---------------------------------------------------------------------------
__global__ __launch_bounds__(256) void k_node(
    const float* __restrict__ coord, const float* __restrict__ mask,
    const float* __restrict__ nw1, const float* __restrict__ nb1,
    const float* __restrict__ nw2, const float* __restrict__ nb2,
    float* __restrict__ out)
{
    __shared__ float nin[8][2*Ff];
    __shared__ float t1s[8][Ff];
    __shared__ float red[256];
    const int t  = threadIdx.x;
    const int r0 = blockIdx.x * 8;
    const int b  = r0 >> 9;

    for (int idx = t; idx < 8*Ff; idx += 256) {
        int nd = idx >> 7, f = idx & 127;
        float mk = mask[r0+nd];
        nin[nd][f]      = g_hm[(r0+nd)*Ff + f] * mk;
        nin[nd][Ff + f] = g_agg[(r0+nd)*Ff + f] * mk;
    }
    {
        float s = 0.f;
        for (int q = t; q < Nn; q += 256) s += mask[b*Nn + q];
        red[t] = s;
    }
    __syncthreads();
    for (int off = 128; off >= 1; off >>= 1) {
        if (t < off) red[t] += red[t + off];
        __syncthreads();
    }

    const int f2  = (t & 63) * 2;
    const int nd0 = (t >> 6) * 2;
    // layer 1
    u64 a0, a1;
    {
        u64 bb = *(const u64*)(nb1 + f2);
        a0 = bb; a1 = bb;
    }
    #pragma unroll 4
    for (int k = 0; k < 2*Ff; k++) {
        u64 wv = *(const u64*)(nw1 + k*Ff + f2);
        ffma2(a0, pack2(nin[nd0][k]),   wv);
        ffma2(a1, pack2(nin[nd0+1][k]), wv);
    }
    {
        float2 v0 = unpack2(a0), v1 = unpack2(a1);
        t1s[nd0][f2]     = silu_f(v0.x);
        t1s[nd0][f2+1]   = silu_f(v0.y);
        t1s[nd0+1][f2]   = silu_f(v1.x);
        t1s[nd0+1][f2+1] = silu_f(v1.y);
    }
    __syncthreads();
    // layer 2
    u64 c0a, c1a;
    {
        u64 bb = *(const u64*)(nb2 + f2);
        c0a = bb; c1a = bb;
    }
    #pragma unroll 4
    for (int k = 0; k < Ff; k++) {
        u64 wv = *(const u64*)(nw2 + k*Ff + f2);
        ffma2(c0a, pack2(t1s[nd0][k]),   wv);
        ffma2(c1a, pack2(t1s[nd0+1][k]), wv);
    }
    {
        float2 v0 = unpack2(c0a), v1 = unpack2(c1a);
        float mk0 = mask[r0+nd0], mk1 = mask[r0+nd0+1];
        float h00 = g_hm[(r0+nd0)*Ff + f2],   h01 = g_hm[(r0+nd0)*Ff + f2+1];
        float h10 = g_hm[(r0+nd0+1)*Ff + f2], h11 = g_hm[(r0+nd0+1)*Ff + f2+1];
        out[(r0+nd0)*Ff + f2]     = (h00 + v0.x)*mk0;
        out[(r0+nd0)*Ff + f2+1]   = (h01 + v0.y)*mk0;
        out[(r0+nd0+1)*Ff + f2]   = (h10 + v1.x)*mk1;
        out[(r0+nd0+1)*Ff + f2+1] = (h11 + v1.y)*mk1;
    }
    if (t < 24) {
        int nd = t/3, d = t - nd*3;
        int r = r0 + nd;
        float mk = mask[r];
        float denom = mk*red[0] + 1e-10f;
        float cm = coord[r*3 + d]*mk;
        out[Bb*Nn*Ff + r*3 + d] = (cm + g_trans[r*3 + d]/denom)*mk;
    }
}

// ---------------------------------------------------------------------------
extern "C" void kernel_launch(void* const* d_in, const int* in_sizes, int n_in,
                              void* d_out, int out_size)
{
    const float* h     = (const float*)d_in[0];
    const float* coord = (const float*)d_in[1];
    const float* mask  = (const float*)d_in[2];
    const float* ew1   = (const float*)d_in[3];
    const float* eb1   = (const float*)d_in[4];
    const float* ew2   = (const float*)d_in[5];
    const float* eb2   = (const float*)d_in[6];
    const float* nw1   = (const float*)d_in[7];
    const float* nb1   = (const float*)d_in[8];
    const float* nw2   = (const float*)d_in[9];
    const float* nb2   = (const float*)d_in[10];
    const float* cw1   = (const float*)d_in[11];
    const float* cb1   = (const float*)d_in[12];
    const float* cw2   = (const float*)d_in[13];

    cudaFuncSetAttribute(k_edge, cudaFuncAttributeMaxDynamicSharedMemorySize, SM_TOTAL);

    k_prep<<<Bb*Nn/8, 256>>>(h, mask, ew1, eb1);
    k_wprep<<<32, 256>>>(ew2, cw1);
    k_edge<<<Bb*(Nn/8), 512, SM_TOTAL>>>(coord, mask, ew1, eb2, cb1, cw2);
    k_node<<<Bb*Nn/8, 256>>>(coord, mask, nw1, nb1, nw2, nb2, (float*)d_out);
}